// round 10
// baseline (speedup 1.0000x reference)
#include <cuda_runtime.h>
#include <cuda_fp16.h>
#include <math.h>
#include <string.h>

#define TWO_PI_F 6.283185307179586f

#define OUT1_ELEMS 67108864
#define O_DIM   512
#define CIN_DIM 512
#define K_DIM   16
#define NI_DIM  16
#define NO_DIM  16
#define KS_DIM  7

#define LERP_BLOCKS (O_DIM * (CIN_DIM / 64))           // 4096: (o, c_block of 64)
#define ROT_TOTAL   (O_DIM * NO_DIM * KS_DIM * KS_DIM) // 401408
#define ROT_BLOCKS  ((ROT_TOTAL + 255) / 256)          // 1568

// bit-cast helpers
__device__ __forceinline__ unsigned int h2_as_u32(__half2 h) {
    unsigned int u; memcpy(&u, &h, 4); return u;
}
__device__ __forceinline__ __half2 u32_as_h2(unsigned int u) {
    __half2 h; memcpy(&h, &u, 4); return h;
}

__device__ __forceinline__ void stg256_cs(float* p, const float* r) {
    asm volatile(
        "st.global.cs.v8.f32 [%0], {%1,%2,%3,%4,%5,%6,%7,%8};"
        :: "l"(p), "f"(r[0]), "f"(r[1]), "f"(r[2]), "f"(r[3]),
           "f"(r[4]), "f"(r[5]), "f"(r[6]), "f"(r[7])
        : "memory");
}

// ---------------------------------------------------------------------------
// Fused kernel.
//  Blocks [0, LERP_BLOCKS): weight_H_out [o, ni, c, no].
//   fp16 pair table: tab[i0*64 + g*4 + rep] (uint4) = endpoint pairs for rows
//   {g, g+16, g+32, g+48}; 4 identical rep copies.
//   Lane map: noh = lane&1 (no half), c_idx = lane>>1 (0..15).
//   rep = ((c_idx>>1)&1) + 2*noh  ==> phase bank-quads (c_idx*4+rep) mod 8
//   are all 8 distinct: conflict-free for any runtime i0.
//   Per n2: 8 LDS.128 (one per no) -> res[4][8] -> 4 STG.256 (32B/thread,
//   warp phase = dense 1024B). Stores per thread halved vs float4 scheme.
//  Blocks [LERP_BLOCKS, ...): rotated bilinear resample (tiny).
// ---------------------------------------------------------------------------
__global__ __launch_bounds__(256) void gsep_fused_kernel(
    const float* __restrict__ in_H,
    const float* __restrict__ out_H,
    const float* __restrict__ weight_H,   // [512, 512, 16]
    const float* __restrict__ weight,     // [512, 1, 7, 7]
    const float* __restrict__ grid_Rn,    // [7, 7, 2]
    const float* __restrict__ mask,       // [7, 7]
    float* __restrict__ out)              // out1 | out2
{
    const int b = blockIdx.x;
    const int t = threadIdx.x;

    if (b < LERP_BLOCKS) {
        __shared__ unsigned int praw[64 * 17];   // half2 pairs, [row][k]
        __shared__ uint4        tab [1024];      // [i0(16)][g(16)][rep(4)] = 16KB

        const int o      = b >> 3;
        const int c_base = (b & 7) * 64;
        const int lane   = t & 31;
        const int warp   = t >> 5;        // 0..7
        const int noh    = lane & 1;      // no half: 0 -> no 0..7, 1 -> no 8..15
        const int c_idx  = lane >> 1;     // 0..15
        const int rep    = ((c_idx >> 1) & 1) + 2 * noh;

        // --- stage: global float4 -> fp16 (k,k+1) pairs in praw ---
        {
            const float4 v = ((const float4*)(weight_H
                              + ((size_t)o * 512 + c_base) * 16))[t];
            const int r = t >> 2, q = t & 3;
            float down_x = __shfl_down_sync(0xffffffffu, v.x, 1);
            float base_x = __shfl_sync(0xffffffffu, v.x, lane & ~3);
            float nxt = (q == 3) ? base_x : down_x;
            unsigned int* d = praw + r * 17 + q * 4;
            d[0] = h2_as_u32(__floats2half2_rn(v.x, v.y));
            d[1] = h2_as_u32(__floats2half2_rn(v.y, v.z));
            d[2] = h2_as_u32(__floats2half2_rn(v.z, v.w));
            d[3] = h2_as_u32(__floats2half2_rn(v.w, nxt));
        }
        __syncthreads();

        // --- build tab: 1024 entries, 4 per thread ---
        #pragma unroll
        for (int e = t; e < 1024; e += 256) {
            const int k = e >> 6;            // 0..15
            const int g = (e >> 2) & 15;     // 0..15
            tab[e] = make_uint4(praw[(g     ) * 17 + k],
                                praw[(g + 16) * 17 + k],
                                praw[(g + 32) * 17 + k],
                                praw[(g + 48) * 17 + k]);
        }
        __syncthreads();

        const uint4* tbase = tab + c_idx * 4 + rep;

        // --- hot loop ---
        #pragma unroll 1
        for (int n2 = 0; n2 < 2; n2++) {
            const int ni = warp * 2 + n2;
            // (i0, frac) for this ni and the thread's 8 no values
            int i0[8]; float fr[8];
            const float ih = __ldg(in_H + ni);
            #pragma unroll
            for (int j = 0; j < 8; j++) {
                float d = ih - __ldg(out_H + noh * 8 + j);
                float r = fmodf(d, TWO_PI_F);
                if (r < 0.0f) r += TWO_PI_F;
                float tt = r * (16.0f / TWO_PI_F);
                float fl = floorf(tt);
                i0[j] = ((int)fl) & 15;
                fr[j] = tt - fl;
            }

            float res[4][8];
            #pragma unroll
            for (int j = 0; j < 8; j++) {
                const uint4 E = tbase[i0[j] << 6];
                const float f = fr[j];
                float2 a;
                a = __half22float2(u32_as_h2(E.x));
                res[0][j] = fmaf(f, a.y - a.x, a.x);
                a = __half22float2(u32_as_h2(E.y));
                res[1][j] = fmaf(f, a.y - a.x, a.x);
                a = __half22float2(u32_as_h2(E.z));
                res[2][j] = fmaf(f, a.y - a.x, a.x);
                a = __half22float2(u32_as_h2(E.w));
                res[3][j] = fmaf(f, a.y - a.x, a.x);
            }

            float* obase = out + ((((size_t)o * 16 + ni) * 512 + c_base) << 4)
                               + noh * 8;
            #pragma unroll
            for (int m = 0; m < 4; m++) {
                const int c_local = 16 * m + c_idx;
                stg256_cs(obase + ((size_t)c_local << 4), res[m]);
            }
        }
        return;
    }

    // -------------------- rotated bilinear resample part --------------------
    const int idx = (b - LERP_BLOCKS) * 256 + t;
    if (idx >= ROT_TOTAL) return;

    const int pix = idx % (KS_DIM * KS_DIM);
    const int on  = idx / (KS_DIM * KS_DIM);
    const int no  = on & 15;
    const int o   = on >> 4;

    const float gx = grid_Rn[pix * 2 + 0];
    const float gy = grid_Rn[pix * 2 + 1];

    const float ang = -out_H[no];
    float sn, cs;
    sincosf(ang, &sn, &cs);
    const float xr = cs * gx - sn * gy;
    const float yr = sn * gx + cs * gy;

    const float x = (xr + 1.0f) * 0.5f * (float)(KS_DIM - 1);
    const float y = (yr + 1.0f) * 0.5f * (float)(KS_DIM - 1);
    const float x0f = floorf(x), y0f = floorf(y);
    const float wx = x - x0f,    wy = y - y0f;
    const int x0 = (int)x0f,     y0 = (int)y0f;

    const float* img = weight + o * (KS_DIM * KS_DIM);

    auto g = [&](int yy, int xx) -> float {
        if (yy < 0 || yy >= KS_DIM || xx < 0 || xx >= KS_DIM) return 0.0f;
        return img[yy * KS_DIM + xx];
    };

    const float v = (1.0f - wy) * (1.0f - wx) * g(y0,     x0)
                  + (1.0f - wy) * wx          * g(y0,     x0 + 1)
                  + wy          * (1.0f - wx) * g(y0 + 1, x0)
                  + wy          * wx          * g(y0 + 1, x0 + 1);

    out[OUT1_ELEMS + idx] = mask[pix] * v;
}

// ---------------------------------------------------------------------------
extern "C" void kernel_launch(void* const* d_in, const int* in_sizes, int n_in,
                              void* d_out, int out_size)
{
    const float* in_H     = (const float*)d_in[0];  // [16, 1]
    const float* out_H    = (const float*)d_in[1];  // [16, 1]
    const float* weight_H = (const float*)d_in[2];  // [512, 512, 16]
    const float* weight   = (const float*)d_in[3];  // [512, 1, 7, 7]
    // d_in[4] = grid_H (uniform grid, implicit; unused)
    const float* grid_Rn  = (const float*)d_in[5];  // [7, 7, 2]
    const float* mask     = (const float*)d_in[6];  // [7, 7]

    gsep_fused_kernel<<<LERP_BLOCKS + ROT_BLOCKS, 256>>>(
        in_H, out_H, weight_H, weight, grid_Rn, mask, (float*)d_out);
}

// round 12
// speedup vs baseline: 1.0877x; 1.0877x over previous
#include <cuda_runtime.h>
#include <cuda_fp16.h>
#include <math.h>
#include <string.h>

#define TWO_PI_F 6.283185307179586f

#define OUT1_ELEMS 67108864
#define O_DIM   512
#define CIN_DIM 512
#define K_DIM   16
#define NI_DIM  16
#define NO_DIM  16
#define KS_DIM  7

#define LERP_BLOCKS (O_DIM * (CIN_DIM / 64))           // 4096: (o, c_block of 64)
#define ROT_TOTAL   (O_DIM * NO_DIM * KS_DIM * KS_DIM) // 401408
#define ROT_BLOCKS  ((ROT_TOTAL + 255) / 256)          // 1568

// bit-cast helpers
__device__ __forceinline__ unsigned int h2_as_u32(__half2 h) {
    unsigned int u; memcpy(&u, &h, 4); return u;
}
__device__ __forceinline__ __half2 u32_as_h2(unsigned int u) {
    __half2 h; memcpy(&h, &u, 4); return h;
}

// ---------------------------------------------------------------------------
// Fused kernel.
//  Blocks [0, LERP_BLOCKS): weight_H_out [o, ni, c, no].
//   fp16 pair table: tab[i0*64 + g*4 + noq] (uint4) = 4x half2 =
//   (W[g][i0],W[g][i0+1]) for rows {g, g+16, g+32, g+48}. One LDS.128 feeds
//   FOUR outputs; noq-replication keeps octet bank-quads distinct for any
//   runtime i0. Index math: d = in_H - out_H is already in (-2pi, 2pi), so
//   python-mod == (d<0 ? d+2pi : d) exactly -- no fmodf. (i0*64, frac) for
//   BOTH ni hoisted to registers; hot loop is a pure LDS->FMA->STG burst.
//  Blocks [LERP_BLOCKS, ...): rotated bilinear resample (tiny).
// ---------------------------------------------------------------------------
__global__ __launch_bounds__(256) void gsep_fused_kernel(
    const float* __restrict__ in_H,
    const float* __restrict__ out_H,
    const float* __restrict__ weight_H,   // [512, 512, 16]
    const float* __restrict__ weight,     // [512, 1, 7, 7]
    const float* __restrict__ grid_Rn,    // [7, 7, 2]
    const float* __restrict__ mask,       // [7, 7]
    float* __restrict__ out)              // out1 | out2
{
    const int b = blockIdx.x;
    const int t = threadIdx.x;

    if (b < LERP_BLOCKS) {
        __shared__ unsigned int praw[64 * 17];   // half2 pairs, [row][k]
        __shared__ uint4        tab [1024];      // [i0(16)][g(16)][noq(4)] = 16KB

        const int o      = b >> 3;
        const int c_base = (b & 7) * 64;
        const int lane   = t & 31;
        const int warp   = t >> 5;        // 0..7
        const int noq    = lane & 3;      // no quad (dense stores)
        const int c_idx  = lane >> 2;     // 0..7

        // --- stage: global float4 -> fp16 (k,k+1) pairs in praw ---
        {
            const float4 v = ((const float4*)(weight_H
                              + ((size_t)o * 512 + c_base) * 16))[t];
            const int r = t >> 2, q = t & 3;
            float down_x = __shfl_down_sync(0xffffffffu, v.x, 1);
            float base_x = __shfl_sync(0xffffffffu, v.x, lane & ~3);
            float nxt = (q == 3) ? base_x : down_x;
            unsigned int* d = praw + r * 17 + q * 4;
            d[0] = h2_as_u32(__floats2half2_rn(v.x, v.y));
            d[1] = h2_as_u32(__floats2half2_rn(v.y, v.z));
            d[2] = h2_as_u32(__floats2half2_rn(v.z, v.w));
            d[3] = h2_as_u32(__floats2half2_rn(v.w, nxt));
        }

        // --- hoist (i0*64, frac) for BOTH ni (cheap: no fmodf needed) ---
        int   i0r[2][4];
        float frr[2][4];
        #pragma unroll
        for (int n2 = 0; n2 < 2; n2++) {
            const float ih = __ldg(in_H + warp * 2 + n2);
            #pragma unroll
            for (int j = 0; j < 4; j++) {
                float d = ih - __ldg(out_H + noq * 4 + j);  // in (-2pi, 2pi)
                if (d < 0.0f) d += TWO_PI_F;                // == python mod here
                float tt = d * (16.0f / TWO_PI_F);          // [0, 16]
                float fl = floorf(tt);
                i0r[n2][j] = (((int)fl) & 15) << 6;         // pre-shifted
                frr[n2][j] = tt - fl;
            }
        }
        __syncthreads();

        // --- build tab: 1024 entries, 4 per thread ---
        #pragma unroll
        for (int e = t; e < 1024; e += 256) {
            const int k = e >> 6;            // 0..15
            const int g = (e >> 2) & 15;     // 0..15
            tab[e] = make_uint4(praw[(g     ) * 17 + k],
                                praw[(g + 16) * 17 + k],
                                praw[(g + 32) * 17 + k],
                                praw[(g + 48) * 17 + k]);
        }
        __syncthreads();

        // --- hot loop: pure LDS -> FMA -> STG bursts ---
        #pragma unroll 1
        for (int n2 = 0; n2 < 2; n2++) {
            const int ni = warp * 2 + n2;
            float* obase = out + ((((size_t)o * 16 + ni) * 512 + c_base) << 4)
                               + noq * 4;
            #pragma unroll
            for (int chunk = 0; chunk < 2; chunk++) {
                const int g = chunk * 8 + c_idx;
                float res[4][4];
                #pragma unroll
                for (int j = 0; j < 4; j++) {
                    const uint4 E = tab[i0r[n2][j] + (g << 2) + noq];
                    const float f = frr[n2][j];
                    float2 a;
                    a = __half22float2(u32_as_h2(E.x));
                    res[0][j] = fmaf(f, a.y - a.x, a.x);
                    a = __half22float2(u32_as_h2(E.y));
                    res[1][j] = fmaf(f, a.y - a.x, a.x);
                    a = __half22float2(u32_as_h2(E.z));
                    res[2][j] = fmaf(f, a.y - a.x, a.x);
                    a = __half22float2(u32_as_h2(E.w));
                    res[3][j] = fmaf(f, a.y - a.x, a.x);
                }
                #pragma unroll
                for (int m = 0; m < 4; m++) {
                    const int c_local = 16 * m + g;
                    __stcs((float4*)(obase + ((size_t)c_local << 4)),
                           make_float4(res[m][0], res[m][1],
                                       res[m][2], res[m][3]));
                }
            }
        }
        return;
    }

    // -------------------- rotated bilinear resample part --------------------
    const int idx = (b - LERP_BLOCKS) * 256 + t;
    if (idx >= ROT_TOTAL) return;

    const int pix = idx % (KS_DIM * KS_DIM);
    const int on  = idx / (KS_DIM * KS_DIM);
    const int no  = on & 15;
    const int o   = on >> 4;

    const float gx = grid_Rn[pix * 2 + 0];
    const float gy = grid_Rn[pix * 2 + 1];

    const float ang = -out_H[no];
    float sn, cs;
    sincosf(ang, &sn, &cs);
    const float xr = cs * gx - sn * gy;
    const float yr = sn * gx + cs * gy;

    const float x = (xr + 1.0f) * 0.5f * (float)(KS_DIM - 1);
    const float y = (yr + 1.0f) * 0.5f * (float)(KS_DIM - 1);
    const float x0f = floorf(x), y0f = floorf(y);
    const float wx = x - x0f,    wy = y - y0f;
    const int x0 = (int)x0f,     y0 = (int)y0f;

    const float* img = weight + o * (KS_DIM * KS_DIM);

    auto g = [&](int yy, int xx) -> float {
        if (yy < 0 || yy >= KS_DIM || xx < 0 || xx >= KS_DIM) return 0.0f;
        return img[yy * KS_DIM + xx];
    };

    const float v = (1.0f - wy) * (1.0f - wx) * g(y0,     x0)
                  + (1.0f - wy) * wx          * g(y0,     x0 + 1)
                  + wy          * (1.0f - wx) * g(y0 + 1, x0)
                  + wy          * wx          * g(y0 + 1, x0 + 1);

    out[OUT1_ELEMS + idx] = mask[pix] * v;
}

// ---------------------------------------------------------------------------
extern "C" void kernel_launch(void* const* d_in, const int* in_sizes, int n_in,
                              void* d_out, int out_size)
{
    const float* in_H     = (const float*)d_in[0];  // [16, 1]
    const float* out_H    = (const float*)d_in[1];  // [16, 1]
    const float* weight_H = (const float*)d_in[2];  // [512, 512, 16]
    const float* weight   = (const float*)d_in[3];  // [512, 1, 7, 7]
    // d_in[4] = grid_H (uniform grid, implicit; unused)
    const float* grid_Rn  = (const float*)d_in[5];  // [7, 7, 2]
    const float* mask     = (const float*)d_in[6];  // [7, 7]

    gsep_fused_kernel<<<LERP_BLOCKS + ROT_BLOCKS, 256>>>(
        in_H, out_H, weight_H, weight, grid_Rn, mask, (float*)d_out);
}

// round 13
// speedup vs baseline: 1.1722x; 1.0777x over previous
#include <cuda_runtime.h>
#include <cuda_fp16.h>
#include <math.h>
#include <string.h>

#define TWO_PI_F 6.283185307179586f

#define OUT1_ELEMS 67108864
#define O_DIM   512
#define CIN_DIM 512
#define K_DIM   16
#define NI_DIM  16
#define NO_DIM  16
#define KS_DIM  7

#define LERP_BLOCKS (O_DIM * (CIN_DIM / 64))           // 4096: (o, c_block of 64)
#define ROT_TOTAL   (O_DIM * NO_DIM * KS_DIM * KS_DIM) // 401408
#define ROT_BLOCKS  ((ROT_TOTAL + 255) / 256)          // 1568

// bit-cast helpers
__device__ __forceinline__ unsigned int h2_as_u32(__half2 h) {
    unsigned int u; memcpy(&u, &h, 4); return u;
}
__device__ __forceinline__ __half2 u32_as_h2(unsigned int u) {
    __half2 h; memcpy(&h, &u, 4); return h;
}

// ---------------------------------------------------------------------------
// Fused kernel (R8 structure: per-n2 recompute => all reg-array indexing is
// STATIC; hoisting across the unroll-1 loop demotes arrays to local memory).
//  Blocks [0, LERP_BLOCKS): weight_H_out [o, ni, c, no].
//   fp16 pair table: tab[i0*64 + g*4 + noq] (uint4) = 4x half2 =
//   (W[g][i0],W[g][i0+1]) for rows {g, g+16, g+32, g+48}. One LDS.128 feeds
//   FOUR outputs (4B/output); noq-replication keeps octet bank-quads distinct
//   for any runtime i0. Index math: d = in_H - out_H is in (-2pi, 2pi), so
//   python-mod == (d<0 ? d+2pi : d) exactly -- fmodf eliminated.
//  Blocks [LERP_BLOCKS, ...): rotated bilinear resample (tiny).
// ---------------------------------------------------------------------------
__global__ __launch_bounds__(256) void gsep_fused_kernel(
    const float* __restrict__ in_H,
    const float* __restrict__ out_H,
    const float* __restrict__ weight_H,   // [512, 512, 16]
    const float* __restrict__ weight,     // [512, 1, 7, 7]
    const float* __restrict__ grid_Rn,    // [7, 7, 2]
    const float* __restrict__ mask,       // [7, 7]
    float* __restrict__ out)              // out1 | out2
{
    const int b = blockIdx.x;
    const int t = threadIdx.x;

    if (b < LERP_BLOCKS) {
        __shared__ unsigned int praw[64 * 17];   // half2 pairs, [row][k]
        __shared__ uint4        tab [1024];      // [i0(16)][g(16)][noq(4)] = 16KB

        const int o      = b >> 3;
        const int c_base = (b & 7) * 64;
        const int lane   = t & 31;
        const int warp   = t >> 5;        // 0..7
        const int noq    = lane & 3;      // no quad (dense stores)
        const int c_idx  = lane >> 2;     // 0..7

        // --- stage: global float4 -> fp16 (k,k+1) pairs in praw ---
        {
            const float4 v = ((const float4*)(weight_H
                              + ((size_t)o * 512 + c_base) * 16))[t];
            const int r = t >> 2, q = t & 3;
            float down_x = __shfl_down_sync(0xffffffffu, v.x, 1);
            float base_x = __shfl_sync(0xffffffffu, v.x, lane & ~3);
            float nxt = (q == 3) ? base_x : down_x;
            unsigned int* d = praw + r * 17 + q * 4;
            d[0] = h2_as_u32(__floats2half2_rn(v.x, v.y));
            d[1] = h2_as_u32(__floats2half2_rn(v.y, v.z));
            d[2] = h2_as_u32(__floats2half2_rn(v.z, v.w));
            d[3] = h2_as_u32(__floats2half2_rn(v.w, nxt));
        }

        // preload the 4 out_H values this thread uses
        float oh[4];
        #pragma unroll
        for (int j = 0; j < 4; j++) oh[j] = __ldg(out_H + noq * 4 + j);

        __syncthreads();

        // --- build tab: 1024 entries, 4 per thread ---
        #pragma unroll
        for (int e = t; e < 1024; e += 256) {
            const int k = e >> 6;            // 0..15
            const int g = (e >> 2) & 15;     // 0..15
            tab[e] = make_uint4(praw[(g     ) * 17 + k],
                                praw[(g + 16) * 17 + k],
                                praw[(g + 32) * 17 + k],
                                praw[(g + 48) * 17 + k]);
        }
        __syncthreads();

        // --- hot loop (per-n2 recompute keeps all indexing static) ---
        #pragma unroll 1
        for (int n2 = 0; n2 < 2; n2++) {
            const int ni = warp * 2 + n2;
            // (i0*64, frac) for this ni and the thread's 4 no values
            int i0[4]; float fr[4];
            const float ih = __ldg(in_H + ni);
            #pragma unroll
            for (int j = 0; j < 4; j++) {
                float d = ih - oh[j];            // in (-2pi, 2pi)
                if (d < 0.0f) d += TWO_PI_F;     // == python mod here
                float tt = d * (16.0f / TWO_PI_F);
                float fl = floorf(tt);
                i0[j] = (((int)fl) & 15) << 6;   // pre-shifted table offset
                fr[j] = tt - fl;
            }
            float* obase = out + ((((size_t)o * 16 + ni) * 512 + c_base) << 4)
                               + noq * 4;
            #pragma unroll
            for (int chunk = 0; chunk < 2; chunk++) {
                const int g = chunk * 8 + c_idx;
                float res[4][4];
                #pragma unroll
                for (int j = 0; j < 4; j++) {
                    const uint4 E = tab[i0[j] + (g << 2) + noq];
                    const float f = fr[j];
                    float2 a;
                    a = __half22float2(u32_as_h2(E.x));
                    res[0][j] = fmaf(f, a.y - a.x, a.x);
                    a = __half22float2(u32_as_h2(E.y));
                    res[1][j] = fmaf(f, a.y - a.x, a.x);
                    a = __half22float2(u32_as_h2(E.z));
                    res[2][j] = fmaf(f, a.y - a.x, a.x);
                    a = __half22float2(u32_as_h2(E.w));
                    res[3][j] = fmaf(f, a.y - a.x, a.x);
                }
                #pragma unroll
                for (int m = 0; m < 4; m++) {
                    const int c_local = 16 * m + g;
                    __stcs((float4*)(obase + ((size_t)c_local << 4)),
                           make_float4(res[m][0], res[m][1],
                                       res[m][2], res[m][3]));
                }
            }
        }
        return;
    }

    // -------------------- rotated bilinear resample part --------------------
    const int idx = (b - LERP_BLOCKS) * 256 + t;
    if (idx >= ROT_TOTAL) return;

    const int pix = idx % (KS_DIM * KS_DIM);
    const int on  = idx / (KS_DIM * KS_DIM);
    const int no  = on & 15;
    const int o   = on >> 4;

    const float gx = grid_Rn[pix * 2 + 0];
    const float gy = grid_Rn[pix * 2 + 1];

    const float ang = -out_H[no];
    float sn, cs;
    sincosf(ang, &sn, &cs);
    const float xr = cs * gx - sn * gy;
    const float yr = sn * gx + cs * gy;

    const float x = (xr + 1.0f) * 0.5f * (float)(KS_DIM - 1);
    const float y = (yr + 1.0f) * 0.5f * (float)(KS_DIM - 1);
    const float x0f = floorf(x), y0f = floorf(y);
    const float wx = x - x0f,    wy = y - y0f;
    const int x0 = (int)x0f,     y0 = (int)y0f;

    const float* img = weight + o * (KS_DIM * KS_DIM);

    auto g = [&](int yy, int xx) -> float {
        if (yy < 0 || yy >= KS_DIM || xx < 0 || xx >= KS_DIM) return 0.0f;
        return img[yy * KS_DIM + xx];
    };

    const float v = (1.0f - wy) * (1.0f - wx) * g(y0,     x0)
                  + (1.0f - wy) * wx          * g(y0,     x0 + 1)
                  + wy          * (1.0f - wx) * g(y0 + 1, x0)
                  + wy          * wx          * g(y0 + 1, x0 + 1);

    out[OUT1_ELEMS + idx] = mask[pix] * v;
}

// ---------------------------------------------------------------------------
extern "C" void kernel_launch(void* const* d_in, const int* in_sizes, int n_in,
                              void* d_out, int out_size)
{
    const float* in_H     = (const float*)d_in[0];  // [16, 1]
    const float* out_H    = (const float*)d_in[1];  // [16, 1]
    const float* weight_H = (const float*)d_in[2];  // [512, 512, 16]
    const float* weight   = (const float*)d_in[3];  // [512, 1, 7, 7]
    // d_in[4] = grid_H (uniform grid, implicit; unused)
    const float* grid_Rn  = (const float*)d_in[5];  // [7, 7, 2]
    const float* mask     = (const float*)d_in[6];  // [7, 7]

    gsep_fused_kernel<<<LERP_BLOCKS + ROT_BLOCKS, 256>>>(
        in_H, out_H, weight_H, weight, grid_Rn, mask, (float*)d_out);
}

// round 14
// speedup vs baseline: 1.1799x; 1.0066x over previous
#include <cuda_runtime.h>
#include <cuda_fp16.h>
#include <math.h>
#include <string.h>

#define TWO_PI_F 6.283185307179586f

#define OUT1_ELEMS 67108864
#define O_DIM   512
#define CIN_DIM 512
#define K_DIM   16
#define NI_DIM  16
#define NO_DIM  16
#define KS_DIM  7

#define LERP_BLOCKS (O_DIM * (CIN_DIM / 64))           // 4096: (o, c_block of 64)
#define ROT_TOTAL   (O_DIM * NO_DIM * KS_DIM * KS_DIM) // 401408
#define ROT_BLOCKS  ((ROT_TOTAL + 255) / 256)          // 1568

// bit-cast helpers
__device__ __forceinline__ unsigned int h2_as_u32(__half2 h) {
    unsigned int u; memcpy(&u, &h, 4); return u;
}
__device__ __forceinline__ __half2 u32_as_h2(unsigned int u) {
    __half2 h; memcpy(&h, &u, 4); return h;
}

// ---------------------------------------------------------------------------
// Fused kernel (R13 structure + FULL unroll of the n2 loop: n2 becomes a
// compile-time constant so all register-array indexing stays static — the
// local-memory demotion that sank the R9/R12 hoists cannot occur — while the
// scheduler gets a 2x window of independent LDS/STG for latency hiding).
//  Blocks [0, LERP_BLOCKS): weight_H_out [o, ni, c, no].
//   fp16 pair table: tab[i0*64 + g*4 + noq] (uint4) = 4x half2 =
//   (W[g][i0],W[g][i0+1]) for rows {g, g+16, g+32, g+48}. One LDS.128 feeds
//   FOUR outputs; noq-replication keeps octet bank-quads distinct for any
//   runtime i0. d = in_H - out_H is in (-2pi, 2pi) => python-mod ==
//   (d<0 ? d+2pi : d) exactly; no fmodf.
//  Blocks [LERP_BLOCKS, ...): rotated bilinear resample (tiny).
// ---------------------------------------------------------------------------
__global__ __launch_bounds__(256) void gsep_fused_kernel(
    const float* __restrict__ in_H,
    const float* __restrict__ out_H,
    const float* __restrict__ weight_H,   // [512, 512, 16]
    const float* __restrict__ weight,     // [512, 1, 7, 7]
    const float* __restrict__ grid_Rn,    // [7, 7, 2]
    const float* __restrict__ mask,       // [7, 7]
    float* __restrict__ out)              // out1 | out2
{
    const int b = blockIdx.x;
    const int t = threadIdx.x;

    if (b < LERP_BLOCKS) {
        __shared__ unsigned int praw[64 * 17];   // half2 pairs, [row][k]
        __shared__ uint4        tab [1024];      // [i0(16)][g(16)][noq(4)] = 16KB

        const int o      = b >> 3;
        const int c_base = (b & 7) * 64;
        const int lane   = t & 31;
        const int warp   = t >> 5;        // 0..7
        const int noq    = lane & 3;      // no quad (dense stores)
        const int c_idx  = lane >> 2;     // 0..7

        // --- stage: global float4 -> fp16 (k,k+1) pairs in praw ---
        {
            const float4 v = ((const float4*)(weight_H
                              + ((size_t)o * 512 + c_base) * 16))[t];
            const int r = t >> 2, q = t & 3;
            float down_x = __shfl_down_sync(0xffffffffu, v.x, 1);
            float base_x = __shfl_sync(0xffffffffu, v.x, lane & ~3);
            float nxt = (q == 3) ? base_x : down_x;
            unsigned int* d = praw + r * 17 + q * 4;
            d[0] = h2_as_u32(__floats2half2_rn(v.x, v.y));
            d[1] = h2_as_u32(__floats2half2_rn(v.y, v.z));
            d[2] = h2_as_u32(__floats2half2_rn(v.z, v.w));
            d[3] = h2_as_u32(__floats2half2_rn(v.w, nxt));
        }

        // preload the 4 out_H values this thread uses
        float oh[4];
        #pragma unroll
        for (int j = 0; j < 4; j++) oh[j] = __ldg(out_H + noq * 4 + j);

        __syncthreads();

        // --- build tab: 1024 entries, 4 per thread ---
        #pragma unroll
        for (int e = t; e < 1024; e += 256) {
            const int k = e >> 6;            // 0..15
            const int g = (e >> 2) & 15;     // 0..15
            tab[e] = make_uint4(praw[(g     ) * 17 + k],
                                praw[(g + 16) * 17 + k],
                                praw[(g + 32) * 17 + k],
                                praw[(g + 48) * 17 + k]);
        }
        __syncthreads();

        // --- hot loop: FULL unroll (n2 compile-time => static indexing) ---
        #pragma unroll
        for (int n2 = 0; n2 < 2; n2++) {
            const int ni = warp * 2 + n2;
            int i0[4]; float fr[4];
            const float ih = __ldg(in_H + ni);
            #pragma unroll
            for (int j = 0; j < 4; j++) {
                float d = ih - oh[j];            // in (-2pi, 2pi)
                if (d < 0.0f) d += TWO_PI_F;     // == python mod here
                float tt = d * (16.0f / TWO_PI_F);
                float fl = floorf(tt);
                i0[j] = (((int)fl) & 15) << 6;   // pre-shifted table offset
                fr[j] = tt - fl;
            }
            float* obase = out + ((((size_t)o * 16 + ni) * 512 + c_base) << 4)
                               + noq * 4;
            #pragma unroll
            for (int chunk = 0; chunk < 2; chunk++) {
                const int g = chunk * 8 + c_idx;
                float res[4][4];
                #pragma unroll
                for (int j = 0; j < 4; j++) {
                    const uint4 E = tab[i0[j] + (g << 2) + noq];
                    const float f = fr[j];
                    float2 a;
                    a = __half22float2(u32_as_h2(E.x));
                    res[0][j] = fmaf(f, a.y - a.x, a.x);
                    a = __half22float2(u32_as_h2(E.y));
                    res[1][j] = fmaf(f, a.y - a.x, a.x);
                    a = __half22float2(u32_as_h2(E.z));
                    res[2][j] = fmaf(f, a.y - a.x, a.x);
                    a = __half22float2(u32_as_h2(E.w));
                    res[3][j] = fmaf(f, a.y - a.x, a.x);
                }
                #pragma unroll
                for (int m = 0; m < 4; m++) {
                    const int c_local = 16 * m + g;
                    __stcs((float4*)(obase + ((size_t)c_local << 4)),
                           make_float4(res[m][0], res[m][1],
                                       res[m][2], res[m][3]));
                }
            }
        }
        return;
    }

    // -------------------- rotated bilinear resample part --------------------
    const int idx = (b - LERP_BLOCKS) * 256 + t;
    if (idx >= ROT_TOTAL) return;

    const int pix = idx % (KS_DIM * KS_DIM);
    const int on  = idx / (KS_DIM * KS_DIM);
    const int no  = on & 15;
    const int o   = on >> 4;

    const float gx = grid_Rn[pix * 2 + 0];
    const float gy = grid_Rn[pix * 2 + 1];

    const float ang = -out_H[no];
    float sn, cs;
    sincosf(ang, &sn, &cs);
    const float xr = cs * gx - sn * gy;
    const float yr = sn * gx + cs * gy;

    const float x = (xr + 1.0f) * 0.5f * (float)(KS_DIM - 1);
    const float y = (yr + 1.0f) * 0.5f * (float)(KS_DIM - 1);
    const float x0f = floorf(x), y0f = floorf(y);
    const float wx = x - x0f,    wy = y - y0f;
    const int x0 = (int)x0f,     y0 = (int)y0f;

    const float* img = weight + o * (KS_DIM * KS_DIM);

    auto g = [&](int yy, int xx) -> float {
        if (yy < 0 || yy >= KS_DIM || xx < 0 || xx >= KS_DIM) return 0.0f;
        return img[yy * KS_DIM + xx];
    };

    const float v = (1.0f - wy) * (1.0f - wx) * g(y0,     x0)
                  + (1.0f - wy) * wx          * g(y0,     x0 + 1)
                  + wy          * (1.0f - wx) * g(y0 + 1, x0)
                  + wy          * wx          * g(y0 + 1, x0 + 1);

    out[OUT1_ELEMS + idx] = mask[pix] * v;
}

// ---------------------------------------------------------------------------
extern "C" void kernel_launch(void* const* d_in, const int* in_sizes, int n_in,
                              void* d_out, int out_size)
{
    const float* in_H     = (const float*)d_in[0];  // [16, 1]
    const float* out_H    = (const float*)d_in[1];  // [16, 1]
    const float* weight_H = (const float*)d_in[2];  // [512, 512, 16]
    const float* weight   = (const float*)d_in[3];  // [512, 1, 7, 7]
    // d_in[4] = grid_H (uniform grid, implicit; unused)
    const float* grid_Rn  = (const float*)d_in[5];  // [7, 7, 2]
    const float* mask     = (const float*)d_in[6];  // [7, 7]

    gsep_fused_kernel<<<LERP_BLOCKS + ROT_BLOCKS, 256>>>(
        in_H, out_H, weight_H, weight, grid_Rn, mask, (float*)d_out);
}